// round 16
// baseline (speedup 1.0000x reference)
#include <cuda_runtime.h>
#include <cuda_fp16.h>
#include <math.h>
#include <stdint.h>

#define BB 16
#define TT 2048
#define EE 64
#define HS 16
#define NQT (TT / 128)    // 16 query tiles
#define NKP 8             // max 256-key supertiles per query tile
#define NPAIR2 72         // sum_{jt=0..15} (jt/2 + 1)

// log2(e) * hs^-0.5
#define QSCALE 0.360673760222241f

// scratch
__device__ float g_q[BB * TT * HS];
__device__ float g_k[BB * TT * HS];
__device__ float g_v[BB * TT * HS];
__device__ float g_rope[TT * HS];
// pre-packed fp16 mma fragments
__device__ uint2 g_kf[BB * 256 * 32];        // [b][nt=key/8][lane]
__device__ uint2 g_vf[BB * 128 * 2 * 32];    // [b][ks=key/16][hn][lane]
// partials: acc as 4 coalesced float4 fields, plus l (scalar; shift-free domain)
__device__ float4 g_part4[BB * NQT * NKP * 4 * 128];
__device__ float g_l[BB * NQT * NKP * 128];

// ---- helpers ----
// first operand -> HIGH half, second -> LOW half
__device__ __forceinline__ uint32_t cvt_f16x2(float hi, float lo) {
    uint32_t d; asm("cvt.rn.f16x2.f32 %0,%1,%2;" : "=r"(d) : "f"(hi), "f"(lo)); return d;
}
__device__ __forceinline__ uint32_t hadd2u(uint32_t a, uint32_t b) {
    __half2 r = __hadd2(*reinterpret_cast<__half2*>(&a), *reinterpret_cast<__half2*>(&b));
    return *reinterpret_cast<uint32_t*>(&r);
}
__device__ __forceinline__ uint32_t ex2h2(uint32_t x) {
    __half2 r = h2exp2(*reinterpret_cast<__half2*>(&x));
    return *reinterpret_cast<uint32_t*>(&r);
}
__device__ __forceinline__ float2 h22f2(uint32_t h) {
    return __half22float2(*reinterpret_cast<__half2*>(&h));
}
// fp32-accumulator fp16 mma (PV)
__device__ __forceinline__ void mma_f16(float c[4],
    uint32_t a0, uint32_t a1, uint32_t a2, uint32_t a3, uint32_t b0, uint32_t b1) {
    asm volatile(
        "mma.sync.aligned.m16n8k16.row.col.f32.f16.f16.f32 "
        "{%0,%1,%2,%3},{%4,%5,%6,%7},{%8,%9},{%0,%1,%2,%3};"
        : "+f"(c[0]), "+f"(c[1]), "+f"(c[2]), "+f"(c[3])
        : "r"(a0), "r"(a1), "r"(a2), "r"(a3), "r"(b0), "r"(b1));
}
// fp16-accumulator fp16 mma (QK^T); C = 0
__device__ __forceinline__ void mma_f16acc(uint32_t& d0, uint32_t& d1,
    uint32_t a0, uint32_t a1, uint32_t a2, uint32_t a3, uint32_t b0, uint32_t b1) {
    asm volatile(
        "mma.sync.aligned.m16n8k16.row.col.f16.f16.f16.f16 "
        "{%0,%1},{%2,%3,%4,%5},{%6,%7},{%8,%9};"
        : "=r"(d0), "=r"(d1)
        : "r"(a0), "r"(a1), "r"(a2), "r"(a3), "r"(b0), "r"(b1), "r"(0u), "r"(0u));
}

// ---------------------------------------------------------------------------
// Kernel 0: RoPE cos/sin table
// ---------------------------------------------------------------------------
__global__ __launch_bounds__(128) void rope_table_kernel()
{
    int idx = blockIdx.x * 128 + threadIdx.x;
    int t = idx >> 3;
    int i = idx & 7;
    float inv = powf(10000.0f, -(float)i * (2.0f / (float)HS));
    float sn, cs;
    sincosf((float)t * inv, &sn, &cs);
    g_rope[t * 16 + 2 * i]     = cs;
    g_rope[t * 16 + 2 * i + 1] = sn;
}

// ---------------------------------------------------------------------------
// Kernel 1: fused QKV projection + RoPE. One thread per (row, quarter):
// blockIdx.y selects 4 head dims (= 2 complete RoPE pairs). 4x parallelism.
// ---------------------------------------------------------------------------
__global__ __launch_bounds__(128) void qkv_rope_kernel(
    const float* __restrict__ x,
    const float* __restrict__ wq,
    const float* __restrict__ wk,
    const float* __restrict__ wv)
{
    __shared__ float swq[EE * 4];
    __shared__ float swk[EE * 4];
    __shared__ float swv[EE * 4];

    int tid = threadIdx.x;
    int quarter = blockIdx.y;
    int hbase = quarter * 4;

    for (int i = tid; i < EE * 4; i += 128) {
        int e = i >> 2, h = i & 3;
        swq[i] = wq[e * HS + hbase + h];
        swk[i] = wk[e * HS + hbase + h];
        swv[i] = wv[e * HS + hbase + h];
    }
    __syncthreads();

    int row = blockIdx.x * 128 + tid;
    int t = row & (TT - 1);

    const float4* xr = reinterpret_cast<const float4*>(x + (size_t)row * EE);

    float q[4], k[4], v[4];
#pragma unroll
    for (int h = 0; h < 4; h++) { q[h] = 0.f; k[h] = 0.f; v[h] = 0.f; }

#pragma unroll
    for (int e4 = 0; e4 < EE / 4; e4++) {
        float4 xv = xr[e4];
        float xs[4] = {xv.x, xv.y, xv.z, xv.w};
#pragma unroll
        for (int j = 0; j < 4; j++) {
            int e = e4 * 4 + j;
#pragma unroll
            for (int h = 0; h < 4; h++) {
                q[h] = fmaf(xs[j], swq[e * 4 + h], q[h]);
                k[h] = fmaf(xs[j], swk[e * 4 + h], k[h]);
                v[h] = fmaf(xs[j], swv[e * 4 + h], v[h]);
            }
        }
    }

    // RoPE: dims [hbase, hbase+4) = rotation pairs hbase/2, hbase/2+1;
    // table entries at g_rope[t*16 + hbase .. +3] = {cos0, sin0, cos1, sin1}
    float4 rv = *reinterpret_cast<const float4*>(g_rope + t * 16 + hbase);
    float rope[4] = {rv.x, rv.y, rv.z, rv.w};

    float qo[4], ko[4];
#pragma unroll
    for (int i = 0; i < 2; i++) {
        float cs = rope[2 * i], sn = rope[2 * i + 1];
        float qe = q[2 * i], qd = q[2 * i + 1];
        float ke = k[2 * i], kd = k[2 * i + 1];
        qo[2 * i]     = qe * cs - qd * sn;
        qo[2 * i + 1] = qe * sn + qd * cs;
        ko[2 * i]     = ke * cs - kd * sn;
        ko[2 * i + 1] = ke * sn + kd * cs;
    }

    *reinterpret_cast<float4*>(g_q + (size_t)row * HS + hbase) = make_float4(qo[0], qo[1], qo[2], qo[3]);
    *reinterpret_cast<float4*>(g_k + (size_t)row * HS + hbase) = make_float4(ko[0], ko[1], ko[2], ko[3]);
    *reinterpret_cast<float4*>(g_v + (size_t)row * HS + hbase) = make_float4(v[0], v[1], v[2], v[3]);
}

// ---------------------------------------------------------------------------
// Kernel 1b: pack K and V into fp16 mma-fragment layout, ONCE per batch.
// ---------------------------------------------------------------------------
__global__ __launch_bounds__(128) void pack_kv_kernel()
{
    int idx = blockIdx.x * 128 + threadIdx.x;
    const int NKE = BB * 256 * 32;   // 131072

    if (idx < NKE) {
        int b   = idx >> 13;          // 256*32 = 8192
        int rem = idx & 8191;
        int nt  = rem >> 5;
        int ln  = rem & 31;
        int key = nt * 8 + (ln >> 2);
        int d0  = 2 * (ln & 3);
        const float* Kr = g_k + ((size_t)b * TT + key) * HS;
        float2 k0 = *reinterpret_cast<const float2*>(Kr + d0);
        float2 k1 = *reinterpret_cast<const float2*>(Kr + d0 + 8);
        g_kf[idx] = make_uint2(cvt_f16x2(k0.y, k0.x), cvt_f16x2(k1.y, k1.x));
    } else {
        int e   = idx - NKE;
        int b   = e >> 13;            // 128*2*32 = 8192
        int rem = e & 8191;
        int ks  = rem >> 6;
        int rest = rem & 63;
        int hn  = rest >> 5;
        int ln  = rest & 31;
        int dim = hn * 8 + (ln >> 2);
        int key0 = ks * 16 + 2 * (ln & 3);
        const float* Vb = g_v + (size_t)b * TT * HS + dim;
        float v0 = Vb[(size_t)key0 * HS];
        float v1 = Vb[(size_t)(key0 + 1) * HS];
        float v2 = Vb[(size_t)(key0 + 8) * HS];
        float v3 = Vb[(size_t)(key0 + 9) * HS];
        g_vf[e] = make_uint2(cvt_f16x2(v1, v0), cvt_f16x2(v3, v2));
    }
}

// ---------------------------------------------------------------------------
// Kernel 2: tensor-core flash attention partial.
// 8 warps x 16 queries (256 threads), 256-key supertiles -> 1152 blocks
// for near-full occupancy. Fragments read from pre-packed global.
// ---------------------------------------------------------------------------
template <bool DIAG>
__device__ __forceinline__ void attn_body(
    int b, int jt, int kp,
    float (*sOut)[17], float* sL)
{
    int tid = threadIdx.x;
    int w = tid >> 5;          // 0..7
    int lane = tid & 31;
    int g = lane >> 2;
    int t4 = lane & 3;
    int st = kp * 256;
    int qwbase = jt * 128 + w * 16;   // 16 query rows per warp

    const uint2* Kf = g_kf + ((size_t)b * 256 + kp * 32) * 32 + lane;
    const uint2* Vf = g_vf + (((size_t)b * 128 + kp * 16) * 2) * 32 + lane;

    // ---- load Q fragments (fp16, scaled by QSCALE) ----
    uint32_t qA[4];
    {
        int r0 = qwbase + g;
        const float* Q0 = g_q + ((size_t)b * TT + r0) * HS;
        const float* Q1 = g_q + ((size_t)b * TT + r0 + 8) * HS;
        float2 f00 = *reinterpret_cast<const float2*>(Q0 + 2 * t4);
        float2 f01 = *reinterpret_cast<const float2*>(Q0 + 2 * t4 + 8);
        float2 f10 = *reinterpret_cast<const float2*>(Q1 + 2 * t4);
        float2 f11 = *reinterpret_cast<const float2*>(Q1 + 2 * t4 + 8);
        qA[0] = cvt_f16x2(f00.y * QSCALE, f00.x * QSCALE);
        qA[1] = cvt_f16x2(f10.y * QSCALE, f10.x * QSCALE);
        qA[2] = cvt_f16x2(f01.y * QSCALE, f01.x * QSCALE);
        qA[3] = cvt_f16x2(f11.y * QSCALE, f11.x * QSCALE);
    }

    float l[2], acc[2][4];
    l[0] = 0.f; l[1] = 0.f;
#pragma unroll
    for (int hn = 0; hn < 2; hn++)
#pragma unroll
        for (int r = 0; r < 4; r++) acc[hn][r] = 0.f;

    int nchunks = 8;
    if (DIAG) {
        int qmaxw = qwbase + 15;
        nchunks = ((qmaxw - st) >> 5) + 1;
        if (nchunks > 8) nchunks = 8;
    }

    for (int c = 0; c < nchunks; c++) {
        // ---- QK^T (f16 accum) + in-place packed softmax ----
        uint32_t pa[2][4];   // [ks][reg] fp16x2 P fragments
        uint32_t lp0 = 0u, lp1 = 0u;

        // prefetch K and V fragments for the whole chunk
        uint2 kf[4];
#pragma unroll
        for (int ntl = 0; ntl < 4; ntl++)
            kf[ntl] = Kf[(size_t)(c * 4 + ntl) * 32];
        uint2 vf[2][2];
#pragma unroll
        for (int ks = 0; ks < 2; ks++)
#pragma unroll
            for (int hn = 0; hn < 2; hn++)
                vf[ks][hn] = Vf[(size_t)((c * 2 + ks) * 2 + hn) * 32];

#pragma unroll
        for (int ntl = 0; ntl < 4; ntl++) {
            int nt = c * 4 + ntl;
            int ks = ntl >> 1;
            int halfn = ntl & 1;
            uint32_t d0, d1;
            mma_f16acc(d0, d1, qA[0], qA[1], qA[2], qA[3], kf[ntl].x, kf[ntl].y);
            if (DIAG) {
                int kb = st + nt * 8 + 2 * t4;
                int r0 = qwbase + g;
                uint32_t b0 = ((kb > r0)     ? 0x0000FC00u : 0u) |
                              ((kb + 1 > r0) ? 0xFC000000u : 0u);
                uint32_t b1 = ((kb > r0 + 8)     ? 0x0000FC00u : 0u) |
                              ((kb + 1 > r0 + 8) ? 0xFC000000u : 0u);
                d0 = hadd2u(d0, b0);
                d1 = hadd2u(d1, b1);
            }
            uint32_t p0 = ex2h2(d0);   // row g,  keys (2t4, 2t4+1)
            uint32_t p1 = ex2h2(d1);   // row g+8
            pa[ks][0 + 2 * halfn] = p0;
            pa[ks][1 + 2 * halfn] = p1;
            lp0 = hadd2u(lp0, p0);
            lp1 = hadd2u(lp1, p1);
        }

        // ---- flush packed l partials to f32 ----
        {
            float2 f0 = h22f2(lp0);
            float2 f1 = h22f2(lp1);
            l[0] += f0.x + f0.y;
            l[1] += f1.x + f1.y;
        }

        // ---- PV: 2 ksteps x 2 hs-tiles, f32-accum fp16 mma ----
#pragma unroll
        for (int ks = 0; ks < 2; ks++)
#pragma unroll
            for (int hn = 0; hn < 2; hn++)
                mma_f16(acc[hn], pa[ks][0], pa[ks][1], pa[ks][2], pa[ks][3],
                        vf[ks][hn].x, vf[ks][hn].y);
    }

    // ---- reduce l across the 4-thread group ----
#pragma unroll
    for (int r = 0; r < 2; r++) {
        l[r] += __shfl_xor_sync(0xffffffffu, l[r], 1);
        l[r] += __shfl_xor_sync(0xffffffffu, l[r], 2);
    }

    // ---- epilog via smem transpose ----
    {
        int rl = w * 16 + g;
#pragma unroll
        for (int hn = 0; hn < 2; hn++) {
            int d = hn * 8 + 2 * t4;
            sOut[rl][d]         = acc[hn][0];
            sOut[rl][d + 1]     = acc[hn][1];
            sOut[rl + 8][d]     = acc[hn][2];
            sOut[rl + 8][d + 1] = acc[hn][3];
        }
        if (t4 == 0) {
            sL[rl]     = l[0];
            sL[rl + 8] = l[1];
        }
    }
    __syncthreads();

    size_t pb = ((size_t)(b * NQT + jt) * NKP + kp);
    if (tid < 128) {
        float4* dst = g_part4 + pb * 4 * 128 + tid;
#pragma unroll
        for (int h = 0; h < 4; h++)
            dst[h * 128] = make_float4(sOut[tid][4 * h], sOut[tid][4 * h + 1],
                                       sOut[tid][4 * h + 2], sOut[tid][4 * h + 3]);
        g_l[pb * 128 + tid] = sL[tid];
    }
}

__global__ __launch_bounds__(256) void attn_part_kernel()
{
    __shared__ float sOut[128][17];
    __shared__ float sL[128];

    int b = blockIdx.y;
    int p = blockIdx.x;
    int jt = 0, rem = p;
    while (rem >= (jt >> 1) + 1) { rem -= (jt >> 1) + 1; jt++; }
    int kp = rem;

    if (kp == (jt >> 1))
        attn_body<true>(b, jt, kp, sOut, sL);
    else
        attn_body<false>(b, jt, kp, sOut, sL);
}

// ---------------------------------------------------------------------------
// Kernel 3: combine partials. 512 threads: one per (query, float4-field).
// All n<=8 partials loaded predicated-unrolled for MLP.
// ---------------------------------------------------------------------------
__global__ __launch_bounds__(512) void combine_kernel(float* __restrict__ out)
{
    int jt = blockIdx.x;
    int b  = blockIdx.y;
    int tid = threadIdx.x;
    int q = tid >> 2;        // query row within tile
    int h = tid & 3;         // float4 field
    int n = (jt >> 1) + 1;

    size_t pb0 = (size_t)(b * NQT + jt) * NKP;
    const float4* base = g_part4 + pb0 * 4 * 128 + h * 128 + q;
    const float*  lb   = g_l     + pb0 * 128 + q;

    float4 av[NKP];
    float  lv[NKP];
#pragma unroll
    for (int i = 0; i < NKP; i++) {
        if (i < n) {
            av[i] = base[(size_t)i * 4 * 128];
            lv[i] = lb[(size_t)i * 128];
        } else {
            av[i] = make_float4(0.f, 0.f, 0.f, 0.f);
            lv[i] = 0.f;
        }
    }

    float4 a = av[0];
    float l_tot = lv[0];
#pragma unroll
    for (int i = 1; i < NKP; i++) {
        a.x += av[i].x; a.y += av[i].y; a.z += av[i].z; a.w += av[i].w;
        l_tot += lv[i];
    }

    float inv_l = 1.0f / l_tot;
    int t = jt * 128 + q;
    float4* Or = reinterpret_cast<float4*>(out + ((size_t)b * TT + t) * HS);
    Or[h] = make_float4(a.x * inv_l, a.y * inv_l, a.z * inv_l, a.w * inv_l);
}

extern "C" void kernel_launch(void* const* d_in, const int* in_sizes, int n_in,
                              void* d_out, int out_size)
{
    const float* x  = (const float*)d_in[0];
    const float* wq = (const float*)d_in[1];
    const float* wk = (const float*)d_in[2];
    const float* wv = (const float*)d_in[3];
    float* out = (float*)d_out;

    rope_table_kernel<<<(TT * 8) / 128, 128>>>();

    dim3 grid_q(256, 4);
    qkv_rope_kernel<<<grid_q, 128>>>(x, wq, wk, wv);

    pack_kv_kernel<<<(2 * BB * 256 * 32) / 128, 128>>>();

    dim3 grid_p(NPAIR2, BB);
    attn_part_kernel<<<grid_p, 256>>>();

    dim3 grid_c(NQT, BB);
    combine_kernel<<<grid_c, 512>>>(out);
}

// round 17
// speedup vs baseline: 1.0285x; 1.0285x over previous
#include <cuda_runtime.h>
#include <cuda_fp16.h>
#include <math.h>
#include <stdint.h>

#define BB 16
#define TT 2048
#define EE 64
#define HS 16
#define NQT (TT / 128)    // 16 query tiles
#define NKP 8             // max 256-key supertiles per query tile
#define NPAIR2 72         // sum_{jt=0..15} (jt/2 + 1)

// log2(e) * hs^-0.5
#define QSCALE 0.360673760222241f

// scratch
__device__ float g_q[BB * TT * HS];
__device__ float g_rope[TT * HS];
// pre-packed fp16 mma fragments (written directly by qkv_rope_kernel)
__device__ uint2 g_kf[BB * 256 * 32];        // [b][nt=key/8][lane]
__device__ uint2 g_vf[BB * 128 * 2 * 32];    // [b][ks=key/16][hn][lane]
// partials: acc as 4 coalesced float4 fields, plus l (scalar; shift-free domain)
__device__ float4 g_part4[BB * NQT * NKP * 4 * 128];
__device__ float g_l[BB * NQT * NKP * 128];

// ---- helpers ----
// first operand -> HIGH half, second -> LOW half
__device__ __forceinline__ uint32_t cvt_f16x2(float hi, float lo) {
    uint32_t d; asm("cvt.rn.f16x2.f32 %0,%1,%2;" : "=r"(d) : "f"(hi), "f"(lo)); return d;
}
__device__ __forceinline__ uint32_t hadd2u(uint32_t a, uint32_t b) {
    __half2 r = __hadd2(*reinterpret_cast<__half2*>(&a), *reinterpret_cast<__half2*>(&b));
    return *reinterpret_cast<uint32_t*>(&r);
}
__device__ __forceinline__ uint32_t ex2h2(uint32_t x) {
    __half2 r = h2exp2(*reinterpret_cast<__half2*>(&x));
    return *reinterpret_cast<uint32_t*>(&r);
}
__device__ __forceinline__ float2 h22f2(uint32_t h) {
    return __half22float2(*reinterpret_cast<__half2*>(&h));
}
// fp32-accumulator fp16 mma (PV)
__device__ __forceinline__ void mma_f16(float c[4],
    uint32_t a0, uint32_t a1, uint32_t a2, uint32_t a3, uint32_t b0, uint32_t b1) {
    asm volatile(
        "mma.sync.aligned.m16n8k16.row.col.f32.f16.f16.f32 "
        "{%0,%1,%2,%3},{%4,%5,%6,%7},{%8,%9},{%0,%1,%2,%3};"
        : "+f"(c[0]), "+f"(c[1]), "+f"(c[2]), "+f"(c[3])
        : "r"(a0), "r"(a1), "r"(a2), "r"(a3), "r"(b0), "r"(b1));
}
// fp16-accumulator fp16 mma (QK^T); C = 0
__device__ __forceinline__ void mma_f16acc(uint32_t& d0, uint32_t& d1,
    uint32_t a0, uint32_t a1, uint32_t a2, uint32_t a3, uint32_t b0, uint32_t b1) {
    asm volatile(
        "mma.sync.aligned.m16n8k16.row.col.f16.f16.f16.f16 "
        "{%0,%1},{%2,%3,%4,%5},{%6,%7},{%8,%9};"
        : "=r"(d0), "=r"(d1)
        : "r"(a0), "r"(a1), "r"(a2), "r"(a3), "r"(b0), "r"(b1), "r"(0u), "r"(0u));
}

// ---------------------------------------------------------------------------
// Kernel 0: RoPE cos/sin table
// ---------------------------------------------------------------------------
__global__ __launch_bounds__(128) void rope_table_kernel()
{
    int idx = blockIdx.x * 128 + threadIdx.x;
    int t = idx >> 3;
    int i = idx & 7;
    float inv = powf(10000.0f, -(float)i * (2.0f / (float)HS));
    float sn, cs;
    sincosf((float)t * inv, &sn, &cs);
    g_rope[t * 16 + 2 * i]     = cs;
    g_rope[t * 16 + 2 * i + 1] = sn;
}

// ---------------------------------------------------------------------------
// Kernel 1: fused QKV projection + RoPE + fragment packing.
// One thread per (row, quarter = 4 head dims = 2 RoPE pairs).
// K/V are written DIRECTLY into fp16 mma-fragment layout (no pack kernel).
// ---------------------------------------------------------------------------
__global__ __launch_bounds__(128) void qkv_rope_kernel(
    const float* __restrict__ x,
    const float* __restrict__ wq,
    const float* __restrict__ wk,
    const float* __restrict__ wv)
{
    __shared__ float swq[EE * 4];
    __shared__ float swk[EE * 4];
    __shared__ float swv[EE * 4];

    int tid = threadIdx.x;
    int quarter = blockIdx.y;
    int hbase = quarter * 4;

    for (int i = tid; i < EE * 4; i += 128) {
        int e = i >> 2, h = i & 3;
        swq[i] = wq[e * HS + hbase + h];
        swk[i] = wk[e * HS + hbase + h];
        swv[i] = wv[e * HS + hbase + h];
    }
    __syncthreads();

    int row = blockIdx.x * 128 + tid;
    int b = row >> 11;             // TT = 2048
    int t = row & (TT - 1);

    const float4* xr = reinterpret_cast<const float4*>(x + (size_t)row * EE);

    float q[4], k[4], v[4];
#pragma unroll
    for (int h = 0; h < 4; h++) { q[h] = 0.f; k[h] = 0.f; v[h] = 0.f; }

#pragma unroll
    for (int e4 = 0; e4 < EE / 4; e4++) {
        float4 xv = xr[e4];
        float xs[4] = {xv.x, xv.y, xv.z, xv.w};
#pragma unroll
        for (int j = 0; j < 4; j++) {
            int e = e4 * 4 + j;
#pragma unroll
            for (int h = 0; h < 4; h++) {
                q[h] = fmaf(xs[j], swq[e * 4 + h], q[h]);
                k[h] = fmaf(xs[j], swk[e * 4 + h], k[h]);
                v[h] = fmaf(xs[j], swv[e * 4 + h], v[h]);
            }
        }
    }

    // RoPE for the 2 pairs this quarter owns
    float4 rv = *reinterpret_cast<const float4*>(g_rope + t * 16 + hbase);
    float rope[4] = {rv.x, rv.y, rv.z, rv.w};

    float qo[4], ko[4];
#pragma unroll
    for (int i = 0; i < 2; i++) {
        float cs = rope[2 * i], sn = rope[2 * i + 1];
        float qe = q[2 * i], qd = q[2 * i + 1];
        float ke = k[2 * i], kd = k[2 * i + 1];
        qo[2 * i]     = qe * cs - qd * sn;
        qo[2 * i + 1] = qe * sn + qd * cs;
        ko[2 * i]     = ke * cs - kd * sn;
        ko[2 * i + 1] = ke * sn + kd * cs;
    }

    // Q: fp32, row-major (attn loads + scales it)
    *reinterpret_cast<float4*>(g_q + (size_t)row * HS + hbase) = make_float4(qo[0], qo[1], qo[2], qo[3]);

    // K fragments: entry [b][t/8][(t%8)*4 + t4] holds dims (2t4,2t4+1) in .x
    // and (2t4+8,2t4+9) in .y. This quarter owns pairs -> two u32 stores.
    {
        int nt = t >> 3;
        int lnbase = (t & 7) * 4;
        int half = quarter >> 1;          // 0 -> .x, 1 -> .y
        int t4a = (quarter & 1) * 2;
        uint32_t u0 = cvt_f16x2(ko[1], ko[0]);
        uint32_t u1 = cvt_f16x2(ko[3], ko[2]);
        uint32_t* kf32 = reinterpret_cast<uint32_t*>(g_kf);
        size_t e0 = ((size_t)b * 256 + nt) * 32 + lnbase + t4a;
        kf32[e0 * 2 + half]       = u0;
        kf32[(e0 + 1) * 2 + half] = u1;
    }

    // V fragments: entry [b][t/16][hn][(d%8)*4 + a] (d = dim, a = (t%8)/2)
    // holds keys {2a, 2a+1, 2a+8, 2a+9} of dim d as fp16[4]. This thread owns
    // one key x 4 dims -> four 16-bit stores.
    {
        int ks = t >> 4;
        int r = t & 15;
        int a = (r & 7) >> 1;
        int sub = (r >> 3) * 2 + (r & 1);   // uint16 index within entry
        __half* vf16 = reinterpret_cast<__half*>(g_vf);
#pragma unroll
        for (int j = 0; j < 4; j++) {
            int d = hbase + j;
            int hn = d >> 3;
            int ln = (d & 7) * 4 + a;
            size_t entry = (((size_t)b * 128 + ks) * 2 + hn) * 32 + ln;
            vf16[entry * 4 + sub] = __float2half_rn(v[j]);
        }
    }
}

// ---------------------------------------------------------------------------
// Kernel 2: tensor-core flash attention partial.
// 8 warps x 16 queries (256 threads), 256-key supertiles (1152 blocks).
// Chunk loop software-pipelined: chunk c+1 fragments prefetched during c.
// ---------------------------------------------------------------------------
template <bool DIAG>
__device__ __forceinline__ void attn_body(
    int b, int jt, int kp,
    float (*sOut)[17], float* sL)
{
    int tid = threadIdx.x;
    int w = tid >> 5;          // 0..7
    int lane = tid & 31;
    int g = lane >> 2;
    int t4 = lane & 3;
    int st = kp * 256;
    int qwbase = jt * 128 + w * 16;   // 16 query rows per warp

    const uint2* Kf = g_kf + ((size_t)b * 256 + kp * 32) * 32 + lane;
    const uint2* Vf = g_vf + (((size_t)b * 128 + kp * 16) * 2) * 32 + lane;

    // ---- load Q fragments (fp16, scaled by QSCALE) ----
    uint32_t qA[4];
    {
        int r0 = qwbase + g;
        const float* Q0 = g_q + ((size_t)b * TT + r0) * HS;
        const float* Q1 = g_q + ((size_t)b * TT + r0 + 8) * HS;
        float2 f00 = *reinterpret_cast<const float2*>(Q0 + 2 * t4);
        float2 f01 = *reinterpret_cast<const float2*>(Q0 + 2 * t4 + 8);
        float2 f10 = *reinterpret_cast<const float2*>(Q1 + 2 * t4);
        float2 f11 = *reinterpret_cast<const float2*>(Q1 + 2 * t4 + 8);
        qA[0] = cvt_f16x2(f00.y * QSCALE, f00.x * QSCALE);
        qA[1] = cvt_f16x2(f10.y * QSCALE, f10.x * QSCALE);
        qA[2] = cvt_f16x2(f01.y * QSCALE, f01.x * QSCALE);
        qA[3] = cvt_f16x2(f11.y * QSCALE, f11.x * QSCALE);
    }

    float l[2], acc[2][4];
    l[0] = 0.f; l[1] = 0.f;
#pragma unroll
    for (int hn = 0; hn < 2; hn++)
#pragma unroll
        for (int r = 0; r < 4; r++) acc[hn][r] = 0.f;

    int nchunks = 8;
    if (DIAG) {
        int qmaxw = qwbase + 15;
        nchunks = ((qmaxw - st) >> 5) + 1;
        if (nchunks > 8) nchunks = 8;
    }

    // ---- prefetch chunk 0 ----
    uint2 kf[4], vf[2][2];
#pragma unroll
    for (int ntl = 0; ntl < 4; ntl++)
        kf[ntl] = Kf[(size_t)ntl * 32];
#pragma unroll
    for (int ks = 0; ks < 2; ks++)
#pragma unroll
        for (int hn = 0; hn < 2; hn++)
            vf[ks][hn] = Vf[(size_t)(ks * 2 + hn) * 32];

#pragma unroll 1
    for (int c = 0; c < nchunks; c++) {
        // ---- issue next chunk's loads first (overlap with this chunk's math) ----
        uint2 kfn[4], vfn[2][2];
        int cn = (c + 1 < nchunks) ? c + 1 : c;
#pragma unroll
        for (int ntl = 0; ntl < 4; ntl++)
            kfn[ntl] = Kf[(size_t)(cn * 4 + ntl) * 32];
#pragma unroll
        for (int ks = 0; ks < 2; ks++)
#pragma unroll
            for (int hn = 0; hn < 2; hn++)
                vfn[ks][hn] = Vf[(size_t)((cn * 2 + ks) * 2 + hn) * 32];

        // ---- QK^T (f16 accum) + in-place packed softmax ----
        uint32_t pa[2][4];   // [ks][reg] fp16x2 P fragments
        uint32_t lp0 = 0u, lp1 = 0u;

#pragma unroll
        for (int ntl = 0; ntl < 4; ntl++) {
            int nt = c * 4 + ntl;
            int ks = ntl >> 1;
            int halfn = ntl & 1;
            uint32_t d0, d1;
            mma_f16acc(d0, d1, qA[0], qA[1], qA[2], qA[3], kf[ntl].x, kf[ntl].y);
            if (DIAG) {
                int kb = st + nt * 8 + 2 * t4;
                int r0 = qwbase + g;
                uint32_t b0 = ((kb > r0)     ? 0x0000FC00u : 0u) |
                              ((kb + 1 > r0) ? 0xFC000000u : 0u);
                uint32_t b1 = ((kb > r0 + 8)     ? 0x0000FC00u : 0u) |
                              ((kb + 1 > r0 + 8) ? 0xFC000000u : 0u);
                d0 = hadd2u(d0, b0);
                d1 = hadd2u(d1, b1);
            }
            uint32_t p0 = ex2h2(d0);   // row g,  keys (2t4, 2t4+1)
            uint32_t p1 = ex2h2(d1);   // row g+8
            pa[ks][0 + 2 * halfn] = p0;
            pa[ks][1 + 2 * halfn] = p1;
            lp0 = hadd2u(lp0, p0);
            lp1 = hadd2u(lp1, p1);
        }

        // ---- flush packed l partials to f32 ----
        {
            float2 f0 = h22f2(lp0);
            float2 f1 = h22f2(lp1);
            l[0] += f0.x + f0.y;
            l[1] += f1.x + f1.y;
        }

        // ---- PV: 2 ksteps x 2 hs-tiles, f32-accum fp16 mma ----
#pragma unroll
        for (int ks = 0; ks < 2; ks++)
#pragma unroll
            for (int hn = 0; hn < 2; hn++)
                mma_f16(acc[hn], pa[ks][0], pa[ks][1], pa[ks][2], pa[ks][3],
                        vf[ks][hn].x, vf[ks][hn].y);

        // ---- rotate buffers ----
#pragma unroll
        for (int ntl = 0; ntl < 4; ntl++) kf[ntl] = kfn[ntl];
#pragma unroll
        for (int ks = 0; ks < 2; ks++)
#pragma unroll
            for (int hn = 0; hn < 2; hn++) vf[ks][hn] = vfn[ks][hn];
    }

    // ---- reduce l across the 4-thread group ----
#pragma unroll
    for (int r = 0; r < 2; r++) {
        l[r] += __shfl_xor_sync(0xffffffffu, l[r], 1);
        l[r] += __shfl_xor_sync(0xffffffffu, l[r], 2);
    }

    // ---- epilog via smem transpose ----
    {
        int rl = w * 16 + g;
#pragma unroll
        for (int hn = 0; hn < 2; hn++) {
            int d = hn * 8 + 2 * t4;
            sOut[rl][d]         = acc[hn][0];
            sOut[rl][d + 1]     = acc[hn][1];
            sOut[rl + 8][d]     = acc[hn][2];
            sOut[rl + 8][d + 1] = acc[hn][3];
        }
        if (t4 == 0) {
            sL[rl]     = l[0];
            sL[rl + 8] = l[1];
        }
    }
    __syncthreads();

    size_t pb = ((size_t)(b * NQT + jt) * NKP + kp);
    if (tid < 128) {
        float4* dst = g_part4 + pb * 4 * 128 + tid;
#pragma unroll
        for (int h = 0; h < 4; h++)
            dst[h * 128] = make_float4(sOut[tid][4 * h], sOut[tid][4 * h + 1],
                                       sOut[tid][4 * h + 2], sOut[tid][4 * h + 3]);
        g_l[pb * 128 + tid] = sL[tid];
    }
}

__global__ __launch_bounds__(256, 5) void attn_part_kernel()
{
    __shared__ float sOut[128][17];
    __shared__ float sL[128];

    int b = blockIdx.y;
    int p = blockIdx.x;
    int jt = 0, rem = p;
    while (rem >= (jt >> 1) + 1) { rem -= (jt >> 1) + 1; jt++; }
    int kp = rem;

    if (kp == (jt >> 1))
        attn_body<true>(b, jt, kp, sOut, sL);
    else
        attn_body<false>(b, jt, kp, sOut, sL);
}

// ---------------------------------------------------------------------------
// Kernel 3: combine partials. 512 threads: one per (query, float4-field).
// All n<=8 partials loaded predicated-unrolled for MLP.
// ---------------------------------------------------------------------------
__global__ __launch_bounds__(512) void combine_kernel(float* __restrict__ out)
{
    int jt = blockIdx.x;
    int b  = blockIdx.y;
    int tid = threadIdx.x;
    int q = tid >> 2;        // query row within tile
    int h = tid & 3;         // float4 field
    int n = (jt >> 1) + 1;

    size_t pb0 = (size_t)(b * NQT + jt) * NKP;
    const float4* base = g_part4 + pb0 * 4 * 128 + h * 128 + q;
    const float*  lb   = g_l     + pb0 * 128 + q;

    float4 av[NKP];
    float  lv[NKP];
#pragma unroll
    for (int i = 0; i < NKP; i++) {
        if (i < n) {
            av[i] = base[(size_t)i * 4 * 128];
            lv[i] = lb[(size_t)i * 128];
        } else {
            av[i] = make_float4(0.f, 0.f, 0.f, 0.f);
            lv[i] = 0.f;
        }
    }

    float4 a = av[0];
    float l_tot = lv[0];
#pragma unroll
    for (int i = 1; i < NKP; i++) {
        a.x += av[i].x; a.y += av[i].y; a.z += av[i].z; a.w += av[i].w;
        l_tot += lv[i];
    }

    float inv_l = 1.0f / l_tot;
    int t = jt * 128 + q;
    float4* Or = reinterpret_cast<float4*>(out + ((size_t)b * TT + t) * HS);
    Or[h] = make_float4(a.x * inv_l, a.y * inv_l, a.z * inv_l, a.w * inv_l);
}

extern "C" void kernel_launch(void* const* d_in, const int* in_sizes, int n_in,
                              void* d_out, int out_size)
{
    const float* x  = (const float*)d_in[0];
    const float* wq = (const float*)d_in[1];
    const float* wk = (const float*)d_in[2];
    const float* wv = (const float*)d_in[3];
    float* out = (float*)d_out;

    rope_table_kernel<<<(TT * 8) / 128, 128>>>();

    dim3 grid_q(256, 4);
    qkv_rope_kernel<<<grid_q, 128>>>(x, wq, wk, wv);

    dim3 grid_p(NPAIR2, BB);
    attn_part_kernel<<<grid_p, 256>>>();

    dim3 grid_c(NQT, BB);
    combine_kernel<<<grid_c, 512>>>(out);
}